// round 7
// baseline (speedup 1.0000x reference)
#include <cuda_runtime.h>
#include <stdint.h>

#define WARPS_PER_BLOCK 5
#define NTHREADS (WARPS_PER_BLOCK * 32)
#define MINBLOCKS 3          // reg cap 65536/(160*3) = 136; 15 warps/SM
#define XST 33               // xs2 row stride in packed elements

typedef unsigned long long ull;

__device__ __forceinline__ ull pack2(float lo, float hi) {
    ull r; asm("mov.b64 %0, {%1, %2};" : "=l"(r) : "f"(lo), "f"(hi)); return r;
}
__device__ __forceinline__ void unpack2(ull v, float& lo, float& hi) {
    asm("mov.b64 {%0, %1}, %2;" : "=f"(lo), "=f"(hi) : "l"(v));
}
__device__ __forceinline__ ull fma2(ull a, ull b, ull c) {
    ull d; asm("fma.rn.f32x2 %0, %1, %2, %3;" : "=l"(d) : "l"(a), "l"(b), "l"(c)); return d;
}
__device__ __forceinline__ ull add2(ull a, ull b) {
    ull d; asm("add.rn.f32x2 %0, %1, %2;" : "=l"(d) : "l"(a), "l"(b)); return d;
}

// ---------------- precomputed weight-sign masks (written by prep kernel) ----------------
__device__ uint32_t g_br_pos[60];           // 18 (w3) + 36 (w4) + 6 (w6)
__device__ uint32_t g_c5_pos[120 * 16];     // TRANSPOSED: [o][ch] for vector loads

__global__ void prep_kernel(const float* __restrict__ w3,
                            const float* __restrict__ w4,
                            const float* __restrict__ w6,
                            const float* __restrict__ c5w) {
    int tid = blockIdx.x * blockDim.x + threadIdx.x;
    if (tid < 60) {
        const float* wp;
        if (tid < 18)      wp = w3 + tid * 25;
        else if (tid < 54) wp = w4 + (tid - 18) * 25;
        else               wp = w6 + (tid - 54) * 25;
        uint32_t m = 0;
        for (int i = 0; i < 25; i++) if (wp[i] > 0.0f) m |= (1u << i);
        g_br_pos[tid] = m;
    }
    for (int idx = tid; idx < 16 * 120; idx += blockDim.x * gridDim.x) {
        int ch = idx / 120, o = idx % 120;
        const float* wp = c5w + o * 400 + ch * 25;
        uint32_t m = 0;
        for (int i = 0; i < 25; i++) if (wp[i] > 0.0f) m |= (1u << i);
        g_c5_pos[o * 16 + ch] = m;   // [o][ch]
    }
}

// ---------------- fused forward kernel: one warp = TWO samples (f32x2 packed) ------------
struct LateSmem {
    ull      sf2[120];             // c5 outputs packed as +-1.0f pairs   (16B aligned)
    ull      yv2[84];              // f6 outputs packed                    (offset 960, 16B)
    uint32_t b14[2 * 84];          // pooled 14-bit rows                   (offset 1632)
    uint32_t pix[2 * 100];         // 16 branch bits per 10x10 pixel       (offset 2304, 16B)
    uint32_t cb[2 * 16];           // stage-2 pooled 25-bit words          (offset 3104, 16B)
};
struct WarpSmem {
    union {
        ull      xs2[32 * XST];    // packed 32x32 tile (c1 phase only), 8448B
        LateSmem L;                // post-c1 buffers
    };
    uint8_t  posm8[2 * 6 * 28 * 4];// [s][ch][row][chunk] 7-bit chunk sign masks
};
struct __align__(16) BlockSmem {
    WarpSmem w[WARPS_PER_BLOCK];
    ull      c1w2v[6][5][6];       // weights: [ch][dy][k(5)+pad], 48B rows for LDS.128
    ull      c1b2[8];              // c1 bias packed (padded)
    uint32_t c5pos[120 * 16];      // transposed [o][ch]
    uint32_t brpos[60];
    float    brb[16];
    float    c5b[120];
};

__global__ __launch_bounds__(NTHREADS, MINBLOCKS)
void lenet_kernel(const float* __restrict__ x,
                  const float* __restrict__ c1w_g, const float* __restrict__ c1b_g,
                  const float* __restrict__ b3,   const float* __restrict__ b4,
                  const float* __restrict__ b6,   const float* __restrict__ c5b_g,
                  const float* __restrict__ f6w,  const float* __restrict__ f6b,
                  const float* __restrict__ rbfw, const float* __restrict__ rbfb,
                  float* __restrict__ out, int nsamples) {
    extern __shared__ unsigned char smem_raw[];
    BlockSmem& S = *reinterpret_cast<BlockSmem*>(smem_raw);

    const int tid = threadIdx.x;
    for (int i = tid; i < 60; i += NTHREADS)        S.brpos[i] = g_br_pos[i];
    for (int i = tid; i < 120 * 16; i += NTHREADS)  S.c5pos[i] = g_c5_pos[i];
    for (int i = tid; i < 150; i += NTHREADS) {
        const int ch = i / 25, r = i % 25;
        float w = c1w_g[i];
        S.c1w2v[ch][r / 5][r % 5] = pack2(w, w);
    }
    if (tid < 30) S.c1w2v[tid / 5][tid % 5][5] = 0;   // pad slot
    for (int i = tid; i < 120; i += NTHREADS)       S.c5b[i] = c5b_g[i];
    if (tid < 6)        { float b = c1b_g[tid]; S.c1b2[tid] = pack2(b, b); }
    if (tid < 6)        S.brb[tid] = b3[tid];
    else if (tid < 15)  S.brb[tid] = b4[tid - 6];
    else if (tid == 15) S.brb[15]  = b6[0];
    __syncthreads();

    const int warp = tid >> 5, lane = tid & 31;
    const int sA = (blockIdx.x * WARPS_PER_BLOCK + warp) * 2;
    const int sB = sA + 1;
    if (sA >= nsamples) return;
    const bool validB = (sB < nsamples);
    WarpSmem& W = S.w[warp];

    // ---- load two x tiles, interleave into packed smem ----
    {
        const float4* xgA = reinterpret_cast<const float4*>(x + (size_t)sA * 1024);
        const float4* xgB = reinterpret_cast<const float4*>(x + (size_t)(validB ? sB : sA) * 1024);
        for (int i = lane; i < 256; i += 32) {
            float4 a = xgA[i], b = xgB[i];
            int e = i * 4;
            ull* p = W.xs2 + (e >> 5) * XST + (e & 31);
            p[0] = pack2(a.x, b.x); p[1] = pack2(a.y, b.y);
            p[2] = pack2(a.z, b.z); p[3] = pack2(a.w, b.w);
        }
    }
    __syncwarp();

    // ---- c1: packed conv; task = (3-ch group, row, 7-col chunk); 224 tasks ----
    for (int t = lane; t < 224; t += 32) {
        const int g = (t >= 112) ? 1 : 0;
        const int rc = g ? (t - 112) : t;
        const int row = rc >> 2, chunk = rc & 3;
        const int ch0 = g * 3;
        ull acc[3][7];
        #pragma unroll
        for (int c = 0; c < 3; c++) {
            const ull b2 = S.c1b2[ch0 + c];
            #pragma unroll
            for (int j = 0; j < 7; j++) acc[c][j] = b2;
        }
        const ull* xbase = W.xs2 + chunk * 7;
        #pragma unroll
        for (int dy = 0; dy < 5; dy++) {
            const ull* xr = xbase + (row + dy) * XST;
            ull xv[11];
            #pragma unroll
            for (int j = 0; j < 11; j++) xv[j] = xr[j];
            #pragma unroll
            for (int c = 0; c < 3; c++) {
                // 3 x LDS.128 broadcast for the 5 weights of this (ch,dy)
                const ulonglong2* wp = reinterpret_cast<const ulonglong2*>(S.c1w2v[ch0 + c][dy]);
                const ulonglong2 w01 = wp[0], w23 = wp[1], w45 = wp[2];
                const ull wk[5] = { w01.x, w01.y, w23.x, w23.y, w45.x };
                #pragma unroll
                for (int k = 0; k < 5; k++) {
                    #pragma unroll
                    for (int col = 0; col < 7; col++)
                        acc[c][col] = fma2(xv[col + k], wk[k], acc[c][col]);
                }
            }
        }
        #pragma unroll
        for (int c = 0; c < 3; c++) {
            uint32_t mA = 0, mB = 0;
            #pragma unroll
            for (int col = 0; col < 7; col++) {
                float a, b; unpack2(acc[c][col], a, b);
                if (a > 0.0f) mA |= (1u << col);
                if (b > 0.0f) mB |= (1u << col);
            }
            const int base = (ch0 + c) * 112 + row * 4 + chunk;
            W.posm8[base]       = (uint8_t)mA;
            W.posm8[672 + base] = (uint8_t)mB;
        }
    }
    __syncwarp();   // xs2 dead from here; W.L overlays it

    // ---- stage-1 relu+avgpool+sign == OR over 2x2 bits, even-bit compress ----
    for (int v = lane; v < 168; v += 32) {
        const int s = (v >= 84) ? 1 : 0;
        const int u = s ? (v - 84) : v;
        const int ch = u / 14, pr = u % 14;
        const uint32_t* pm = reinterpret_cast<const uint32_t*>(W.posm8 + s * 672 + ch * 112);
        uint32_t v32 = pm[2 * pr] | pm[2 * pr + 1];
        uint32_t m = (v32 & 0x7Fu)
                   | (((v32 >> 8)  & 0x7Fu) << 7)
                   | (((v32 >> 16) & 0x7Fu) << 14)
                   | (((v32 >> 24) & 0x7Fu) << 21);
        uint32_t c = (m | (m >> 1)) & 0x55555555u;
        c = (c | (c >> 1)) & 0x33333333u;
        c = (c | (c >> 2)) & 0x0F0F0F0Fu;
        c = (c | (c >> 4)) & 0x00FF00FFu;
        c = (c | (c >> 8)) & 0x0000FFFFu;
        W.L.b14[s * 84 + u] = c;
    }
    __syncwarp();

    // ---- 16 binary branch convs (bitpacked popcount), 200 pixel tasks ----
    {
        const int I3[18] = {0,1,2, 1,2,3, 2,3,4, 3,4,5, 0,4,5, 0,1,5};
        const int I4[36] = {0,1,2,3, 1,2,3,4, 2,3,4,5, 0,3,4,5, 0,1,4,5,
                            0,1,2,5, 0,1,3,4, 1,2,4,5, 0,2,3,5};
        for (int t = lane; t < 200; t += 32) {
            const int s = (t >= 100) ? 1 : 0;
            const int px = s ? (t - 100) : t;
            const int r = px / 10, c = px % 10;
            const uint32_t* bp = W.L.b14 + s * 84;
            uint32_t win[6]; int pc[6];
            #pragma unroll
            for (int ch = 0; ch < 6; ch++) {
                uint32_t wv = 0;
                #pragma unroll
                for (int dy = 0; dy < 5; dy++)
                    wv |= ((bp[ch * 14 + r + dy] >> c) & 31u) << (5 * dy);
                win[ch] = wv; pc[ch] = __popc(wv);
            }
            uint32_t bits = 0;
            #pragma unroll
            for (int k = 0; k < 6; k++) {
                const int a = I3[3*k], b = I3[3*k+1], d = I3[3*k+2];
                int sum = 2 * (__popc(win[a] & S.brpos[3*k])
                             + __popc(win[b] & S.brpos[3*k+1])
                             + __popc(win[d] & S.brpos[3*k+2]))
                          - (pc[a] + pc[b] + pc[d]);
                if ((float)sum + S.brb[k] > 0.0f) bits |= (1u << k);
            }
            #pragma unroll
            for (int k = 0; k < 9; k++) {
                const int a = I4[4*k], b = I4[4*k+1], d = I4[4*k+2], e = I4[4*k+3];
                int sum = 2 * (__popc(win[a] & S.brpos[18 + 4*k])
                             + __popc(win[b] & S.brpos[18 + 4*k+1])
                             + __popc(win[d] & S.brpos[18 + 4*k+2])
                             + __popc(win[e] & S.brpos[18 + 4*k+3]))
                          - (pc[a] + pc[b] + pc[d] + pc[e]);
                if ((float)sum + S.brb[6 + k] > 0.0f) bits |= (1u << (6 + k));
            }
            {
                int sum = 0;
                #pragma unroll
                for (int ch = 0; ch < 6; ch++)
                    sum += 2 * __popc(win[ch] & S.brpos[54 + ch]) - pc[ch];
                if ((float)sum + S.brb[15] > 0.0f) bits |= (1u << 15);
            }
            W.L.pix[s * 100 + px] = bits;
        }
    }
    __syncwarp();

    // ---- stage-2 relu+pool+sign -> 400 bits per sample (64-bit pair loads) ----
    {
        const int s = lane >> 4, ch = lane & 15;
        const ull* pp2 = reinterpret_cast<const ull*>(W.L.pix + s * 100);
        uint32_t r = 0;
        #pragma unroll
        for (int u = 0; u < 25; u++) {
            const int pr = u / 5, pc2 = u % 5;
            ull pair = pp2[pr * 10 + pc2] | pp2[pr * 10 + 5 + pc2];  // rows 2pr, 2pr+1
            uint32_t v = (uint32_t)pair | (uint32_t)(pair >> 32);
            r |= ((v >> ch) & 1u) << u;
        }
        W.L.cb[s * 16 + ch] = r;
    }
    __syncwarp();

    // ---- c5: cb preloaded to regs; transposed masks via LDS.128 ----
    {
        uint32_t cbr[32];
        {
            const uint4* cq = reinterpret_cast<const uint4*>(W.L.cb);
            #pragma unroll
            for (int q = 0; q < 8; q++) {
                uint4 v = cq[q];
                cbr[4*q] = v.x; cbr[4*q+1] = v.y; cbr[4*q+2] = v.z; cbr[4*q+3] = v.w;
            }
        }
        int tpA = 0, tpB = 0;
        #pragma unroll
        for (int ch = 0; ch < 16; ch++) { tpA += __popc(cbr[ch]); tpB += __popc(cbr[16 + ch]); }
        for (int o = lane; o < 120; o += 32) {
            const uint4* cp = reinterpret_cast<const uint4*>(S.c5pos + o * 16);
            int aA = 0, aB = 0;
            #pragma unroll
            for (int q = 0; q < 4; q++) {
                uint4 p = cp[q];
                aA += __popc(cbr[4*q] & p.x) + __popc(cbr[4*q+1] & p.y)
                    + __popc(cbr[4*q+2] & p.z) + __popc(cbr[4*q+3] & p.w);
                aB += __popc(cbr[16+4*q] & p.x) + __popc(cbr[16+4*q+1] & p.y)
                    + __popc(cbr[16+4*q+2] & p.z) + __popc(cbr[16+4*q+3] & p.w);
            }
            const float b = S.c5b[o];
            float vA = (float)(2 * aA - tpA) + b;
            float vB = (float)(2 * aB - tpB) + b;
            W.L.sf2[o] = pack2(vA > 0.0f ? 1.0f : -1.0f, vB > 0.0f ? 1.0f : -1.0f);
        }
    }
    __syncwarp();

    // ---- f6: 3 outputs per lane, shared sf2 sweep (vectorized) ----
    if (lane < 28) {
        const int i0 = lane * 3;
        ull a[3][2];
        #pragma unroll
        for (int r = 0; r < 3; r++) { a[r][0] = 0; a[r][1] = 0; }
        const ulonglong2* sp = reinterpret_cast<const ulonglong2*>(W.L.sf2);
        const float4* w0 = reinterpret_cast<const float4*>(f6w + (i0    ) * 120);
        const float4* w1 = reinterpret_cast<const float4*>(f6w + (i0 + 1) * 120);
        const float4* w2 = reinterpret_cast<const float4*>(f6w + (i0 + 2) * 120);
        #pragma unroll 6
        for (int j4 = 0; j4 < 30; j4++) {
            ulonglong2 s01 = sp[2 * j4], s23 = sp[2 * j4 + 1];
            float4 wv0 = __ldg(w0 + j4), wv1 = __ldg(w1 + j4), wv2 = __ldg(w2 + j4);
            a[0][0] = fma2(s01.x, pack2(wv0.x, wv0.x), a[0][0]);
            a[0][1] = fma2(s01.y, pack2(wv0.y, wv0.y), a[0][1]);
            a[0][0] = fma2(s23.x, pack2(wv0.z, wv0.z), a[0][0]);
            a[0][1] = fma2(s23.y, pack2(wv0.w, wv0.w), a[0][1]);
            a[1][0] = fma2(s01.x, pack2(wv1.x, wv1.x), a[1][0]);
            a[1][1] = fma2(s01.y, pack2(wv1.y, wv1.y), a[1][1]);
            a[1][0] = fma2(s23.x, pack2(wv1.z, wv1.z), a[1][0]);
            a[1][1] = fma2(s23.y, pack2(wv1.w, wv1.w), a[1][1]);
            a[2][0] = fma2(s01.x, pack2(wv2.x, wv2.x), a[2][0]);
            a[2][1] = fma2(s01.y, pack2(wv2.y, wv2.y), a[2][1]);
            a[2][0] = fma2(s23.x, pack2(wv2.z, wv2.z), a[2][0]);
            a[2][1] = fma2(s23.y, pack2(wv2.w, wv2.w), a[2][1]);
        }
        #pragma unroll
        for (int r = 0; r < 3; r++) {
            float gA, gB; unpack2(add2(a[r][0], a[r][1]), gA, gB);
            const float fb = __ldg(f6b + i0 + r);
            W.L.yv2[i0 + r] = pack2(tanhf(1.7519f * (gA + fb)), tanhf(1.7519f * (gB + fb)));
        }
    }
    __syncwarp();

    // ---- rbf head: relu(W y + b), vectorized ----
    if (lane < 10) {
        const float rb = __ldg(rbfb + lane);
        ull a0 = pack2(rb, rb), a1 = 0;
        const ulonglong2* yp = reinterpret_cast<const ulonglong2*>(W.L.yv2);
        const float4* wr = reinterpret_cast<const float4*>(rbfw + lane * 84);
        #pragma unroll 7
        for (int j4 = 0; j4 < 21; j4++) {
            float4 w = __ldg(wr + j4);
            ulonglong2 y01 = yp[2 * j4];
            ulonglong2 y23 = yp[2 * j4 + 1];
            a0 = fma2(y01.x, pack2(w.x, w.x), a0);
            a1 = fma2(y01.y, pack2(w.y, w.y), a1);
            a0 = fma2(y23.x, pack2(w.z, w.z), a0);
            a1 = fma2(y23.y, pack2(w.w, w.w), a1);
        }
        float oA, oB; unpack2(add2(a0, a1), oA, oB);
        out[(size_t)sA * 10 + lane] = fmaxf(oA, 0.0f);
        if (validB) out[(size_t)sB * 10 + lane] = fmaxf(oB, 0.0f);
    }
}

extern "C" void kernel_launch(void* const* d_in, const int* in_sizes, int n_in,
                              void* d_out, int out_size) {
    const float* x    = (const float*)d_in[0];
    const float* c1w  = (const float*)d_in[1];
    const float* c1b  = (const float*)d_in[2];
    const float* w3   = (const float*)d_in[3];
    const float* b3   = (const float*)d_in[4];
    const float* w4   = (const float*)d_in[5];
    const float* b4   = (const float*)d_in[6];
    const float* w6   = (const float*)d_in[7];
    const float* b6   = (const float*)d_in[8];
    const float* c5w  = (const float*)d_in[9];
    const float* c5b  = (const float*)d_in[10];
    const float* f6w  = (const float*)d_in[11];
    const float* f6b  = (const float*)d_in[12];
    const float* rbfw = (const float*)d_in[13];
    const float* rbfb = (const float*)d_in[14];
    float* out = (float*)d_out;

    const int nsamples = in_sizes[0] / 1024;
    const int smem_bytes = (int)sizeof(BlockSmem);

    prep_kernel<<<8, 256>>>(w3, w4, w6, c5w);

    cudaFuncSetAttribute(lenet_kernel, cudaFuncAttributeMaxDynamicSharedMemorySize, smem_bytes);
    const int samples_per_block = WARPS_PER_BLOCK * 2;
    const int blocks = (nsamples + samples_per_block - 1) / samples_per_block;
    lenet_kernel<<<blocks, NTHREADS, smem_bytes>>>(
        x, c1w, c1b, b3, b4, b6, c5b, f6w, f6b, rbfw, rbfb, out, nsamples);
}

// round 8
// speedup vs baseline: 1.1695x; 1.1695x over previous
#include <cuda_runtime.h>
#include <stdint.h>

#define WARPS_PER_BLOCK 4
#define NTHREADS (WARPS_PER_BLOCK * 32)
#define MINBLOCKS 5          // reg cap 65536/(128*5) = 102; 5 blocks/SM = 20 warps/SM
#define XST 33               // xs2 row stride in packed elements

typedef unsigned long long ull;

__device__ __forceinline__ ull pack2(float lo, float hi) {
    ull r; asm("mov.b64 %0, {%1, %2};" : "=l"(r) : "f"(lo), "f"(hi)); return r;
}
__device__ __forceinline__ void unpack2(ull v, float& lo, float& hi) {
    asm("mov.b64 {%0, %1}, %2;" : "=f"(lo), "=f"(hi) : "l"(v));
}
__device__ __forceinline__ ull fma2(ull a, ull b, ull c) {
    ull d; asm("fma.rn.f32x2 %0, %1, %2, %3;" : "=l"(d) : "l"(a), "l"(b), "l"(c)); return d;
}
__device__ __forceinline__ ull add2(ull a, ull b) {
    ull d; asm("add.rn.f32x2 %0, %1, %2;" : "=l"(d) : "l"(a), "l"(b)); return d;
}

// ---------------- precomputed weight-sign masks (written by prep kernel) ----------------
__device__ uint32_t g_br_pos[60];                        // 18 (w3) + 36 (w4) + 6 (w6)
__device__ __align__(16) uint32_t g_c5_pos[120 * 16];    // TRANSPOSED [o][ch]; read via __ldg

__global__ void prep_kernel(const float* __restrict__ w3,
                            const float* __restrict__ w4,
                            const float* __restrict__ w6,
                            const float* __restrict__ c5w) {
    int tid = blockIdx.x * blockDim.x + threadIdx.x;
    if (tid < 60) {
        const float* wp;
        if (tid < 18)      wp = w3 + tid * 25;
        else if (tid < 54) wp = w4 + (tid - 18) * 25;
        else               wp = w6 + (tid - 54) * 25;
        uint32_t m = 0;
        for (int i = 0; i < 25; i++) if (wp[i] > 0.0f) m |= (1u << i);
        g_br_pos[tid] = m;
    }
    for (int idx = tid; idx < 16 * 120; idx += blockDim.x * gridDim.x) {
        int ch = idx / 120, o = idx % 120;
        const float* wp = c5w + o * 400 + ch * 25;
        uint32_t m = 0;
        for (int i = 0; i < 25; i++) if (wp[i] > 0.0f) m |= (1u << i);
        g_c5_pos[o * 16 + ch] = m;
    }
}

// ---------------- fused forward kernel: one warp = TWO samples (f32x2 packed) ------------
struct LateSmem {
    ull      sf2[120];             // c5 outputs packed as +-1.0f pairs
    ull      yv2[84];              // f6 outputs packed
    uint32_t b14[2 * 84];          // pooled 14-bit rows
    uint32_t pix[2 * 100];         // 16 branch bits per 10x10 pixel
    uint32_t cb[2 * 16];           // stage-2 pooled 25-bit words
};
struct WarpSmem {
    union {
        ull      xs2[32 * XST];    // packed 32x32 tile (c1 phase only), 8448B
        LateSmem L;                // post-c1 buffers
    };
    uint8_t  posm8[2 * 6 * 28 * 4];// [s][ch][row][chunk] 7-bit chunk sign masks
};
struct __align__(16) BlockSmem {
    WarpSmem w[WARPS_PER_BLOCK];
    ull      c1w2v[6][5][6];       // weights: [ch][dy][k(5)+pad] for LDS.128 broadcast
    ull      c1b2[8];              // c1 bias packed (padded)
    uint32_t brpos[60];
    float    brb[16];
    float    c5b[120];
};

__global__ __launch_bounds__(NTHREADS, MINBLOCKS)
void lenet_kernel(const float* __restrict__ x,
                  const float* __restrict__ c1w_g, const float* __restrict__ c1b_g,
                  const float* __restrict__ b3,   const float* __restrict__ b4,
                  const float* __restrict__ b6,   const float* __restrict__ c5b_g,
                  const float* __restrict__ f6w,  const float* __restrict__ f6b,
                  const float* __restrict__ rbfw, const float* __restrict__ rbfb,
                  float* __restrict__ out, int nsamples) {
    extern __shared__ unsigned char smem_raw[];
    BlockSmem& S = *reinterpret_cast<BlockSmem*>(smem_raw);

    const int tid = threadIdx.x;
    for (int i = tid; i < 60; i += NTHREADS)  S.brpos[i] = g_br_pos[i];
    for (int i = tid; i < 150; i += NTHREADS) {
        const int ch = i / 25, r = i % 25;
        float w = c1w_g[i];
        S.c1w2v[ch][r / 5][r % 5] = pack2(w, w);
    }
    if (tid < 30) S.c1w2v[tid / 5][tid % 5][5] = 0;
    for (int i = tid; i < 120; i += NTHREADS) S.c5b[i] = c5b_g[i];
    if (tid < 6)        { float b = c1b_g[tid]; S.c1b2[tid] = pack2(b, b); }
    if (tid < 6)        S.brb[tid] = b3[tid];
    else if (tid < 15)  S.brb[tid] = b4[tid - 6];
    else if (tid == 15) S.brb[15]  = b6[0];
    __syncthreads();

    const int warp = tid >> 5, lane = tid & 31;
    const int sA = (blockIdx.x * WARPS_PER_BLOCK + warp) * 2;
    const int sB = sA + 1;
    if (sA >= nsamples) return;
    const bool validB = (sB < nsamples);
    WarpSmem& W = S.w[warp];

    // ---- load two x tiles, interleave into packed smem ----
    {
        const float4* xgA = reinterpret_cast<const float4*>(x + (size_t)sA * 1024);
        const float4* xgB = reinterpret_cast<const float4*>(x + (size_t)(validB ? sB : sA) * 1024);
        for (int i = lane; i < 256; i += 32) {
            float4 a = xgA[i], b = xgB[i];
            int e = i * 4;
            ull* p = W.xs2 + (e >> 5) * XST + (e & 31);
            p[0] = pack2(a.x, b.x); p[1] = pack2(a.y, b.y);
            p[2] = pack2(a.z, b.z); p[3] = pack2(a.w, b.w);
        }
    }
    __syncwarp();

    // ---- c1: packed conv; task = (3-ch group, row, 7-col chunk); 224 tasks ----
    for (int t = lane; t < 224; t += 32) {
        const int g = (t >= 112) ? 1 : 0;
        const int rc = g ? (t - 112) : t;
        const int row = rc >> 2, chunk = rc & 3;
        const int ch0 = g * 3;
        ull acc[3][7];
        #pragma unroll
        for (int c = 0; c < 3; c++) {
            const ull b2 = S.c1b2[ch0 + c];
            #pragma unroll
            for (int j = 0; j < 7; j++) acc[c][j] = b2;
        }
        const ull* xbase = W.xs2 + chunk * 7;
        #pragma unroll
        for (int dy = 0; dy < 5; dy++) {
            const ull* xr = xbase + (row + dy) * XST;
            ull xv[11];
            #pragma unroll
            for (int j = 0; j < 11; j++) xv[j] = xr[j];
            #pragma unroll
            for (int c = 0; c < 3; c++) {
                const ulonglong2* wp = reinterpret_cast<const ulonglong2*>(S.c1w2v[ch0 + c][dy]);
                const ulonglong2 w01 = wp[0], w23 = wp[1], w45 = wp[2];
                const ull wk[5] = { w01.x, w01.y, w23.x, w23.y, w45.x };
                #pragma unroll
                for (int k = 0; k < 5; k++) {
                    #pragma unroll
                    for (int col = 0; col < 7; col++)
                        acc[c][col] = fma2(xv[col + k], wk[k], acc[c][col]);
                }
            }
        }
        #pragma unroll
        for (int c = 0; c < 3; c++) {
            uint32_t mA = 0, mB = 0;
            #pragma unroll
            for (int col = 0; col < 7; col++) {
                float a, b; unpack2(acc[c][col], a, b);
                if (a > 0.0f) mA |= (1u << col);
                if (b > 0.0f) mB |= (1u << col);
            }
            const int base = (ch0 + c) * 112 + row * 4 + chunk;
            W.posm8[base]       = (uint8_t)mA;
            W.posm8[672 + base] = (uint8_t)mB;
        }
    }
    __syncwarp();   // xs2 dead from here; W.L overlays it

    // ---- stage-1 relu+avgpool+sign == OR over 2x2 bits, even-bit compress ----
    for (int v = lane; v < 168; v += 32) {
        const int s = (v >= 84) ? 1 : 0;
        const int u = s ? (v - 84) : v;
        const int ch = u / 14, pr = u % 14;
        const uint32_t* pm = reinterpret_cast<const uint32_t*>(W.posm8 + s * 672 + ch * 112);
        uint32_t v32 = pm[2 * pr] | pm[2 * pr + 1];
        uint32_t m = (v32 & 0x7Fu)
                   | (((v32 >> 8)  & 0x7Fu) << 7)
                   | (((v32 >> 16) & 0x7Fu) << 14)
                   | (((v32 >> 24) & 0x7Fu) << 21);
        uint32_t c = (m | (m >> 1)) & 0x55555555u;
        c = (c | (c >> 1)) & 0x33333333u;
        c = (c | (c >> 2)) & 0x0F0F0F0Fu;
        c = (c | (c >> 4)) & 0x00FF00FFu;
        c = (c | (c >> 8)) & 0x0000FFFFu;
        W.L.b14[s * 84 + u] = c;
    }
    __syncwarp();

    // ---- 16 binary branch convs (bitpacked popcount), 200 pixel tasks ----
    {
        const int I3[18] = {0,1,2, 1,2,3, 2,3,4, 3,4,5, 0,4,5, 0,1,5};
        const int I4[36] = {0,1,2,3, 1,2,3,4, 2,3,4,5, 0,3,4,5, 0,1,4,5,
                            0,1,2,5, 0,1,3,4, 1,2,4,5, 0,2,3,5};
        for (int t = lane; t < 200; t += 32) {
            const int s = (t >= 100) ? 1 : 0;
            const int px = s ? (t - 100) : t;
            const int r = px / 10, c = px % 10;
            const uint32_t* bp = W.L.b14 + s * 84;
            uint32_t win[6]; int pc[6];
            #pragma unroll
            for (int ch = 0; ch < 6; ch++) {
                uint32_t wv = 0;
                #pragma unroll
                for (int dy = 0; dy < 5; dy++)
                    wv |= ((bp[ch * 14 + r + dy] >> c) & 31u) << (5 * dy);
                win[ch] = wv; pc[ch] = __popc(wv);
            }
            uint32_t bits = 0;
            #pragma unroll
            for (int k = 0; k < 6; k++) {
                const int a = I3[3*k], b = I3[3*k+1], d = I3[3*k+2];
                int sum = 2 * (__popc(win[a] & S.brpos[3*k])
                             + __popc(win[b] & S.brpos[3*k+1])
                             + __popc(win[d] & S.brpos[3*k+2]))
                          - (pc[a] + pc[b] + pc[d]);
                if ((float)sum + S.brb[k] > 0.0f) bits |= (1u << k);
            }
            #pragma unroll
            for (int k = 0; k < 9; k++) {
                const int a = I4[4*k], b = I4[4*k+1], d = I4[4*k+2], e = I4[4*k+3];
                int sum = 2 * (__popc(win[a] & S.brpos[18 + 4*k])
                             + __popc(win[b] & S.brpos[18 + 4*k+1])
                             + __popc(win[d] & S.brpos[18 + 4*k+2])
                             + __popc(win[e] & S.brpos[18 + 4*k+3]))
                          - (pc[a] + pc[b] + pc[d] + pc[e]);
                if ((float)sum + S.brb[6 + k] > 0.0f) bits |= (1u << (6 + k));
            }
            {
                int sum = 0;
                #pragma unroll
                for (int ch = 0; ch < 6; ch++)
                    sum += 2 * __popc(win[ch] & S.brpos[54 + ch]) - pc[ch];
                if ((float)sum + S.brb[15] > 0.0f) bits |= (1u << 15);
            }
            W.L.pix[s * 100 + px] = bits;
        }
    }
    __syncwarp();

    // ---- stage-2 relu+pool+sign -> 400 bits per sample (64-bit pair loads) ----
    {
        const int s = lane >> 4, ch = lane & 15;
        const ull* pp2 = reinterpret_cast<const ull*>(W.L.pix + s * 100);
        uint32_t r = 0;
        #pragma unroll
        for (int u = 0; u < 25; u++) {
            const int pr = u / 5, pc2 = u % 5;
            ull pair = pp2[pr * 10 + pc2] | pp2[pr * 10 + 5 + pc2];
            uint32_t v = (uint32_t)pair | (uint32_t)(pair >> 32);
            r |= ((v >> ch) & 1u) << u;
        }
        W.L.cb[s * 16 + ch] = r;
    }
    __syncwarp();

    // ---- c5: cb preloaded to regs; transposed masks streamed from GLOBAL (L2) ----
    {
        uint32_t cbr[32];
        {
            const uint4* cq = reinterpret_cast<const uint4*>(W.L.cb);
            #pragma unroll
            for (int q = 0; q < 8; q++) {
                uint4 v = cq[q];
                cbr[4*q] = v.x; cbr[4*q+1] = v.y; cbr[4*q+2] = v.z; cbr[4*q+3] = v.w;
            }
        }
        int tpA = 0, tpB = 0;
        #pragma unroll
        for (int ch = 0; ch < 16; ch++) { tpA += __popc(cbr[ch]); tpB += __popc(cbr[16 + ch]); }
        for (int o = lane; o < 120; o += 32) {
            const uint4* cp = reinterpret_cast<const uint4*>(g_c5_pos + o * 16);
            int aA = 0, aB = 0;
            #pragma unroll
            for (int q = 0; q < 4; q++) {
                uint4 p = __ldg(cp + q);
                aA += __popc(cbr[4*q] & p.x) + __popc(cbr[4*q+1] & p.y)
                    + __popc(cbr[4*q+2] & p.z) + __popc(cbr[4*q+3] & p.w);
                aB += __popc(cbr[16+4*q] & p.x) + __popc(cbr[16+4*q+1] & p.y)
                    + __popc(cbr[16+4*q+2] & p.z) + __popc(cbr[16+4*q+3] & p.w);
            }
            const float b = S.c5b[o];
            float vA = (float)(2 * aA - tpA) + b;
            float vB = (float)(2 * aB - tpB) + b;
            W.L.sf2[o] = pack2(vA > 0.0f ? 1.0f : -1.0f, vB > 0.0f ? 1.0f : -1.0f);
        }
    }
    __syncwarp();

    // ---- f6: y = tanh(1.7519 * (W s + b)), packed over both samples ----
    for (int i = lane; i < 84; i += 32) {
        const float4* wrow = reinterpret_cast<const float4*>(f6w + i * 120);
        ull a0 = 0, a1 = 0;
        #pragma unroll 6
        for (int j4 = 0; j4 < 30; j4++) {
            float4 wv = __ldg(wrow + j4);
            a0 = fma2(W.L.sf2[4*j4],     pack2(wv.x, wv.x), a0);
            a1 = fma2(W.L.sf2[4*j4 + 1], pack2(wv.y, wv.y), a1);
            a0 = fma2(W.L.sf2[4*j4 + 2], pack2(wv.z, wv.z), a0);
            a1 = fma2(W.L.sf2[4*j4 + 3], pack2(wv.w, wv.w), a1);
        }
        float gA, gB; unpack2(add2(a0, a1), gA, gB);
        const float fb = __ldg(f6b + i);
        W.L.yv2[i] = pack2(tanhf(1.7519f * (gA + fb)), tanhf(1.7519f * (gB + fb)));
    }
    __syncwarp();

    // ---- rbf head: relu(W y + b), vectorized ----
    if (lane < 10) {
        const float rb = __ldg(rbfb + lane);
        ull a0 = pack2(rb, rb), a1 = 0;
        const ulonglong2* yp = reinterpret_cast<const ulonglong2*>(W.L.yv2);
        const float4* wr = reinterpret_cast<const float4*>(rbfw + lane * 84);
        #pragma unroll 7
        for (int j4 = 0; j4 < 21; j4++) {
            float4 w = __ldg(wr + j4);
            ulonglong2 y01 = yp[2 * j4];
            ulonglong2 y23 = yp[2 * j4 + 1];
            a0 = fma2(y01.x, pack2(w.x, w.x), a0);
            a1 = fma2(y01.y, pack2(w.y, w.y), a1);
            a0 = fma2(y23.x, pack2(w.z, w.z), a0);
            a1 = fma2(y23.y, pack2(w.w, w.w), a1);
        }
        float oA, oB; unpack2(add2(a0, a1), oA, oB);
        out[(size_t)sA * 10 + lane] = fmaxf(oA, 0.0f);
        if (validB) out[(size_t)sB * 10 + lane] = fmaxf(oB, 0.0f);
    }
}

extern "C" void kernel_launch(void* const* d_in, const int* in_sizes, int n_in,
                              void* d_out, int out_size) {
    const float* x    = (const float*)d_in[0];
    const float* c1w  = (const float*)d_in[1];
    const float* c1b  = (const float*)d_in[2];
    const float* w3   = (const float*)d_in[3];
    const float* b3   = (const float*)d_in[4];
    const float* w4   = (const float*)d_in[5];
    const float* b4   = (const float*)d_in[6];
    const float* w6   = (const float*)d_in[7];
    const float* b6   = (const float*)d_in[8];
    const float* c5w  = (const float*)d_in[9];
    const float* c5b  = (const float*)d_in[10];
    const float* f6w  = (const float*)d_in[11];
    const float* f6b  = (const float*)d_in[12];
    const float* rbfw = (const float*)d_in[13];
    const float* rbfb = (const float*)d_in[14];
    float* out = (float*)d_out;

    const int nsamples = in_sizes[0] / 1024;
    const int smem_bytes = (int)sizeof(BlockSmem);

    prep_kernel<<<8, 256>>>(w3, w4, w6, c5w);

    cudaFuncSetAttribute(lenet_kernel, cudaFuncAttributeMaxDynamicSharedMemorySize, smem_bytes);
    const int samples_per_block = WARPS_PER_BLOCK * 2;
    const int blocks = (nsamples + samples_per_block - 1) / samples_per_block;
    lenet_kernel<<<blocks, NTHREADS, smem_bytes>>>(
        x, c1w, c1b, b3, b4, b6, c5b, f6w, f6b, rbfw, rbfb, out, nsamples);
}

// round 9
// speedup vs baseline: 1.2804x; 1.0948x over previous
#include <cuda_runtime.h>
#include <stdint.h>

#define WARPS_PER_BLOCK 4
#define NTHREADS (WARPS_PER_BLOCK * 32)
#define MINBLOCKS 5          // reg cap 65536/(128*5) = 102; 5 blocks/SM = 20 warps/SM
#define XST 33               // xs2 row stride in packed elements

typedef unsigned long long ull;

__device__ __forceinline__ ull pack2(float lo, float hi) {
    ull r; asm("mov.b64 %0, {%1, %2};" : "=l"(r) : "f"(lo), "f"(hi)); return r;
}
__device__ __forceinline__ void unpack2(ull v, float& lo, float& hi) {
    asm("mov.b64 {%0, %1}, %2;" : "=f"(lo), "=f"(hi) : "l"(v));
}
__device__ __forceinline__ ull fma2(ull a, ull b, ull c) {
    ull d; asm("fma.rn.f32x2 %0, %1, %2, %3;" : "=l"(d) : "l"(a), "l"(b), "l"(c)); return d;
}
__device__ __forceinline__ ull add2(ull a, ull b) {
    ull d; asm("add.rn.f32x2 %0, %1, %2;" : "=l"(d) : "l"(a), "l"(b)); return d;
}

// ---------------- precomputed tables (written by prep kernel) ----------------
__device__ uint32_t g_br_pos[60];                        // 18 (w3) + 36 (w4) + 6 (w6)
__device__ __align__(16) uint32_t g_c5_pos[120 * 16];    // transposed [o][ch]
__device__ __align__(16) float    g_f6wt[30 * 84 * 4];   // f6w tiled [j4][out][4] (coalesced)
__device__ __align__(16) float    g_rbfwt[21 * 10 * 4];  // rbfw tiled [j4][out][4]

__global__ void prep_kernel(const float* __restrict__ w3,
                            const float* __restrict__ w4,
                            const float* __restrict__ w6,
                            const float* __restrict__ c5w,
                            const float* __restrict__ f6w,
                            const float* __restrict__ rbfw) {
    const int tid = blockIdx.x * blockDim.x + threadIdx.x;
    const int stride = blockDim.x * gridDim.x;
    if (tid < 60) {
        const float* wp;
        if (tid < 18)      wp = w3 + tid * 25;
        else if (tid < 54) wp = w4 + (tid - 18) * 25;
        else               wp = w6 + (tid - 54) * 25;
        uint32_t m = 0;
        for (int i = 0; i < 25; i++) if (wp[i] > 0.0f) m |= (1u << i);
        g_br_pos[tid] = m;
    }
    for (int idx = tid; idx < 16 * 120; idx += stride) {
        int ch = idx / 120, o = idx % 120;
        const float* wp = c5w + o * 400 + ch * 25;
        uint32_t m = 0;
        for (int i = 0; i < 25; i++) if (wp[i] > 0.0f) m |= (1u << i);
        g_c5_pos[o * 16 + ch] = m;
    }
    for (int idx = tid; idx < 30 * 84 * 4; idx += stride) {
        int q = idx & 3, e = idx >> 2;
        int j4 = e / 84, i = e % 84;
        g_f6wt[idx] = f6w[i * 120 + j4 * 4 + q];
    }
    for (int idx = tid; idx < 21 * 10 * 4; idx += stride) {
        int q = idx & 3, e = idx >> 2;
        int j4 = e / 10, o = e % 10;
        g_rbfwt[idx] = rbfw[o * 84 + j4 * 4 + q];
    }
}

// ---------------- fused forward kernel: one warp = TWO samples (f32x2 packed) ------------
struct LateSmem {
    ull      sf2[120];             // c5 outputs packed as +-1.0f pairs
    ull      yv2[84];              // f6 outputs packed
    uint32_t b14[2 * 84];          // pooled 14-bit rows
    uint32_t pix[2 * 100];         // 16 branch bits per 10x10 pixel
    uint32_t cb[2 * 16];           // stage-2 pooled 25-bit words
};
struct WarpSmem {
    union {
        ull      xs2[32 * XST];    // packed 32x32 tile (c1 phase only), 8448B
        LateSmem L;                // post-c1 buffers
    };
    uint8_t  posm8[2 * 6 * 28 * 4];// [s][ch][row][chunk] 7-bit chunk sign masks
};
struct __align__(16) BlockSmem {
    WarpSmem w[WARPS_PER_BLOCK];
    ull      c1w2v[6][5][6];       // weights [ch][dy][k(5)+pad] for LDS.128 broadcast
    ull      c1b2[8];
    uint32_t brpos[60];
    float    brb[16];
    float    c5b[120];
};

__global__ __launch_bounds__(NTHREADS, MINBLOCKS)
void lenet_kernel(const float* __restrict__ x,
                  const float* __restrict__ c1w_g, const float* __restrict__ c1b_g,
                  const float* __restrict__ b3,   const float* __restrict__ b4,
                  const float* __restrict__ b6,   const float* __restrict__ c5b_g,
                  const float* __restrict__ f6b,
                  const float* __restrict__ rbfb,
                  float* __restrict__ out, int nsamples) {
    extern __shared__ unsigned char smem_raw[];
    BlockSmem& S = *reinterpret_cast<BlockSmem*>(smem_raw);

    const int tid = threadIdx.x;
    for (int i = tid; i < 60; i += NTHREADS)  S.brpos[i] = g_br_pos[i];
    for (int i = tid; i < 150; i += NTHREADS) {
        const int ch = i / 25, r = i % 25;
        float w = c1w_g[i];
        S.c1w2v[ch][r / 5][r % 5] = pack2(w, w);
    }
    if (tid < 30) S.c1w2v[tid / 5][tid % 5][5] = 0;
    for (int i = tid; i < 120; i += NTHREADS) S.c5b[i] = c5b_g[i];
    if (tid < 6)        { float b = c1b_g[tid]; S.c1b2[tid] = pack2(b, b); }
    if (tid < 6)        S.brb[tid] = b3[tid];
    else if (tid < 15)  S.brb[tid] = b4[tid - 6];
    else if (tid == 15) S.brb[15]  = b6[0];
    __syncthreads();

    const int warp = tid >> 5, lane = tid & 31;
    const int sA = (blockIdx.x * WARPS_PER_BLOCK + warp) * 2;
    // clamped load indices: every thread runs all phases (block-wide syncs below)
    const int sAl = min(sA, nsamples - 1);
    const int sBl = min(sA + 1, nsamples - 1);
    WarpSmem& W = S.w[warp];

    // ---- load two x tiles, interleave into packed smem ----
    {
        const float4* xgA = reinterpret_cast<const float4*>(x + (size_t)sAl * 1024);
        const float4* xgB = reinterpret_cast<const float4*>(x + (size_t)sBl * 1024);
        for (int i = lane; i < 256; i += 32) {
            float4 a = xgA[i], b = xgB[i];
            int e = i * 4;
            ull* p = W.xs2 + (e >> 5) * XST + (e & 31);
            p[0] = pack2(a.x, b.x); p[1] = pack2(a.y, b.y);
            p[2] = pack2(a.z, b.z); p[3] = pack2(a.w, b.w);
        }
    }
    __syncwarp();

    // ---- c1: packed conv; task = (3-ch group, row, 7-col chunk); 224 tasks ----
    for (int t = lane; t < 224; t += 32) {
        const int g = (t >= 112) ? 1 : 0;
        const int rc = g ? (t - 112) : t;
        const int row = rc >> 2, chunk = rc & 3;
        const int ch0 = g * 3;
        ull acc[3][7];
        #pragma unroll
        for (int c = 0; c < 3; c++) {
            const ull b2 = S.c1b2[ch0 + c];
            #pragma unroll
            for (int j = 0; j < 7; j++) acc[c][j] = b2;
        }
        const ull* xbase = W.xs2 + chunk * 7;
        #pragma unroll
        for (int dy = 0; dy < 5; dy++) {
            const ull* xr = xbase + (row + dy) * XST;
            ull xv[11];
            #pragma unroll
            for (int j = 0; j < 11; j++) xv[j] = xr[j];
            #pragma unroll
            for (int c = 0; c < 3; c++) {
                const ulonglong2* wp = reinterpret_cast<const ulonglong2*>(S.c1w2v[ch0 + c][dy]);
                const ulonglong2 w01 = wp[0], w23 = wp[1], w45 = wp[2];
                const ull wk[5] = { w01.x, w01.y, w23.x, w23.y, w45.x };
                #pragma unroll
                for (int k = 0; k < 5; k++) {
                    #pragma unroll
                    for (int col = 0; col < 7; col++)
                        acc[c][col] = fma2(xv[col + k], wk[k], acc[c][col]);
                }
            }
        }
        #pragma unroll
        for (int c = 0; c < 3; c++) {
            uint32_t mA = 0, mB = 0;
            #pragma unroll
            for (int col = 0; col < 7; col++) {
                float a, b; unpack2(acc[c][col], a, b);
                if (a > 0.0f) mA |= (1u << col);
                if (b > 0.0f) mB |= (1u << col);
            }
            const int base = (ch0 + c) * 112 + row * 4 + chunk;
            W.posm8[base]       = (uint8_t)mA;
            W.posm8[672 + base] = (uint8_t)mB;
        }
    }
    __syncwarp();   // xs2 dead from here; W.L overlays it

    // ---- stage-1 relu+avgpool+sign ----
    for (int v = lane; v < 168; v += 32) {
        const int s = (v >= 84) ? 1 : 0;
        const int u = s ? (v - 84) : v;
        const int ch = u / 14, pr = u % 14;
        const uint32_t* pm = reinterpret_cast<const uint32_t*>(W.posm8 + s * 672 + ch * 112);
        uint32_t v32 = pm[2 * pr] | pm[2 * pr + 1];
        uint32_t m = (v32 & 0x7Fu)
                   | (((v32 >> 8)  & 0x7Fu) << 7)
                   | (((v32 >> 16) & 0x7Fu) << 14)
                   | (((v32 >> 24) & 0x7Fu) << 21);
        uint32_t c = (m | (m >> 1)) & 0x55555555u;
        c = (c | (c >> 1)) & 0x33333333u;
        c = (c | (c >> 2)) & 0x0F0F0F0Fu;
        c = (c | (c >> 4)) & 0x00FF00FFu;
        c = (c | (c >> 8)) & 0x0000FFFFu;
        W.L.b14[s * 84 + u] = c;
    }
    __syncwarp();

    // ---- 16 binary branch convs (bitpacked popcount), 200 pixel tasks ----
    {
        const int I3[18] = {0,1,2, 1,2,3, 2,3,4, 3,4,5, 0,4,5, 0,1,5};
        const int I4[36] = {0,1,2,3, 1,2,3,4, 2,3,4,5, 0,3,4,5, 0,1,4,5,
                            0,1,2,5, 0,1,3,4, 1,2,4,5, 0,2,3,5};
        for (int t = lane; t < 200; t += 32) {
            const int s = (t >= 100) ? 1 : 0;
            const int px = s ? (t - 100) : t;
            const int r = px / 10, c = px % 10;
            const uint32_t* bp = W.L.b14 + s * 84;
            uint32_t win[6]; int pc[6];
            #pragma unroll
            for (int ch = 0; ch < 6; ch++) {
                uint32_t wv = 0;
                #pragma unroll
                for (int dy = 0; dy < 5; dy++)
                    wv |= ((bp[ch * 14 + r + dy] >> c) & 31u) << (5 * dy);
                win[ch] = wv; pc[ch] = __popc(wv);
            }
            uint32_t bits = 0;
            #pragma unroll
            for (int k = 0; k < 6; k++) {
                const int a = I3[3*k], b = I3[3*k+1], d = I3[3*k+2];
                int sum = 2 * (__popc(win[a] & S.brpos[3*k])
                             + __popc(win[b] & S.brpos[3*k+1])
                             + __popc(win[d] & S.brpos[3*k+2]))
                          - (pc[a] + pc[b] + pc[d]);
                if ((float)sum + S.brb[k] > 0.0f) bits |= (1u << k);
            }
            #pragma unroll
            for (int k = 0; k < 9; k++) {
                const int a = I4[4*k], b = I4[4*k+1], d = I4[4*k+2], e = I4[4*k+3];
                int sum = 2 * (__popc(win[a] & S.brpos[18 + 4*k])
                             + __popc(win[b] & S.brpos[18 + 4*k+1])
                             + __popc(win[d] & S.brpos[18 + 4*k+2])
                             + __popc(win[e] & S.brpos[18 + 4*k+3]))
                          - (pc[a] + pc[b] + pc[d] + pc[e]);
                if ((float)sum + S.brb[6 + k] > 0.0f) bits |= (1u << (6 + k));
            }
            {
                int sum = 0;
                #pragma unroll
                for (int ch = 0; ch < 6; ch++)
                    sum += 2 * __popc(win[ch] & S.brpos[54 + ch]) - pc[ch];
                if ((float)sum + S.brb[15] > 0.0f) bits |= (1u << 15);
            }
            W.L.pix[s * 100 + px] = bits;
        }
    }
    __syncwarp();

    // ---- stage-2 relu+pool+sign -> 400 bits per sample ----
    {
        const int s = lane >> 4, ch = lane & 15;
        const ull* pp2 = reinterpret_cast<const ull*>(W.L.pix + s * 100);
        uint32_t r = 0;
        #pragma unroll
        for (int u = 0; u < 25; u++) {
            const int pr = u / 5, pc2 = u % 5;
            ull pair = pp2[pr * 10 + pc2] | pp2[pr * 10 + 5 + pc2];
            uint32_t v = (uint32_t)pair | (uint32_t)(pair >> 32);
            r |= ((v >> ch) & 1u) << u;
        }
        W.L.cb[s * 16 + ch] = r;
    }
    __syncthreads();

    // ---- c5 (BLOCK-COOP): thread = output o; masks read ONCE, reused for all 4 warp-pairs ----
    if (tid < 120) {
        const int o = tid;
        uint4 p[4];
        {
            const uint4* cp = reinterpret_cast<const uint4*>(g_c5_pos + o * 16);
            #pragma unroll
            for (int q = 0; q < 4; q++) p[q] = __ldg(cp + q);
        }
        const float b = S.c5b[o];
        #pragma unroll
        for (int w4 = 0; w4 < WARPS_PER_BLOCK; w4++) {
            uint32_t cbr[32];
            const uint4* cq = reinterpret_cast<const uint4*>(S.w[w4].L.cb);
            #pragma unroll
            for (int q = 0; q < 8; q++) {
                uint4 v = cq[q];
                cbr[4*q] = v.x; cbr[4*q+1] = v.y; cbr[4*q+2] = v.z; cbr[4*q+3] = v.w;
            }
            int tpA = 0, tpB = 0;
            #pragma unroll
            for (int ch = 0; ch < 16; ch++) { tpA += __popc(cbr[ch]); tpB += __popc(cbr[16 + ch]); }
            int aA = 0, aB = 0;
            #pragma unroll
            for (int q = 0; q < 4; q++) {
                aA += __popc(cbr[4*q] & p[q].x) + __popc(cbr[4*q+1] & p[q].y)
                    + __popc(cbr[4*q+2] & p[q].z) + __popc(cbr[4*q+3] & p[q].w);
                aB += __popc(cbr[16+4*q] & p[q].x) + __popc(cbr[16+4*q+1] & p[q].y)
                    + __popc(cbr[16+4*q+2] & p[q].z) + __popc(cbr[16+4*q+3] & p[q].w);
            }
            float vA = (float)(2 * aA - tpA) + b;
            float vB = (float)(2 * aB - tpB) + b;
            S.w[w4].L.sf2[o] = pack2(vA > 0.0f ? 1.0f : -1.0f, vB > 0.0f ? 1.0f : -1.0f);
        }
    }
    __syncthreads();

    // ---- f6 (BLOCK-COOP, coalesced tiled weights): thread = output i, all 4 warp-pairs ----
    if (tid < 84) {
        ull a0[WARPS_PER_BLOCK], a1[WARPS_PER_BLOCK];
        #pragma unroll
        for (int w4 = 0; w4 < WARPS_PER_BLOCK; w4++) { a0[w4] = 0; a1[w4] = 0; }
        const float4* wt = reinterpret_cast<const float4*>(g_f6wt) + tid;
        #pragma unroll 5
        for (int j4 = 0; j4 < 30; j4++) {
            float4 wv = __ldg(wt + j4 * 84);   // coalesced across threads
            const ull wx = pack2(wv.x, wv.x), wy = pack2(wv.y, wv.y);
            const ull wz = pack2(wv.z, wv.z), ww = pack2(wv.w, wv.w);
            #pragma unroll
            for (int w4 = 0; w4 < WARPS_PER_BLOCK; w4++) {
                const ulonglong2* sp = reinterpret_cast<const ulonglong2*>(S.w[w4].L.sf2);
                ulonglong2 s01 = sp[2 * j4], s23 = sp[2 * j4 + 1];
                a0[w4] = fma2(s01.x, wx, a0[w4]);
                a1[w4] = fma2(s01.y, wy, a1[w4]);
                a0[w4] = fma2(s23.x, wz, a0[w4]);
                a1[w4] = fma2(s23.y, ww, a1[w4]);
            }
        }
        const float fb = __ldg(f6b + tid);
        #pragma unroll
        for (int w4 = 0; w4 < WARPS_PER_BLOCK; w4++) {
            float gA, gB; unpack2(add2(a0[w4], a1[w4]), gA, gB);
            S.w[w4].L.yv2[tid] = pack2(tanhf(1.7519f * (gA + fb)), tanhf(1.7519f * (gB + fb)));
        }
    }
    __syncthreads();

    // ---- rbf head (BLOCK-COOP): thread = (out o, warp-pair w4) ----
    if (tid < 10 * WARPS_PER_BLOCK) {
        const int o = tid % 10, w4 = tid / 10;
        const int s0 = (blockIdx.x * WARPS_PER_BLOCK + w4) * 2;
        const float rb = __ldg(rbfb + o);
        ull a0 = pack2(rb, rb), a1 = 0;
        const ulonglong2* yp = reinterpret_cast<const ulonglong2*>(S.w[w4].L.yv2);
        const float4* wr = reinterpret_cast<const float4*>(g_rbfwt) + o;
        #pragma unroll 7
        for (int j4 = 0; j4 < 21; j4++) {
            float4 w = __ldg(wr + j4 * 10);
            ulonglong2 y01 = yp[2 * j4];
            ulonglong2 y23 = yp[2 * j4 + 1];
            a0 = fma2(y01.x, pack2(w.x, w.x), a0);
            a1 = fma2(y01.y, pack2(w.y, w.y), a1);
            a0 = fma2(y23.x, pack2(w.z, w.z), a0);
            a1 = fma2(y23.y, pack2(w.w, w.w), a1);
        }
        float oA, oB; unpack2(add2(a0, a1), oA, oB);
        if (s0 < nsamples)     out[(size_t)s0 * 10 + o]       = fmaxf(oA, 0.0f);
        if (s0 + 1 < nsamples) out[(size_t)(s0 + 1) * 10 + o] = fmaxf(oB, 0.0f);
    }
}

extern "C" void kernel_launch(void* const* d_in, const int* in_sizes, int n_in,
                              void* d_out, int out_size) {
    const float* x    = (const float*)d_in[0];
    const float* c1w  = (const float*)d_in[1];
    const float* c1b  = (const float*)d_in[2];
    const float* w3   = (const float*)d_in[3];
    const float* b3   = (const float*)d_in[4];
    const float* w4   = (const float*)d_in[5];
    const float* b4   = (const float*)d_in[6];
    const float* w6   = (const float*)d_in[7];
    const float* b6   = (const float*)d_in[8];
    const float* c5w  = (const float*)d_in[9];
    const float* c5b  = (const float*)d_in[10];
    const float* f6w  = (const float*)d_in[11];
    const float* f6b  = (const float*)d_in[12];
    const float* rbfw = (const float*)d_in[13];
    const float* rbfb = (const float*)d_in[14];
    float* out = (float*)d_out;

    const int nsamples = in_sizes[0] / 1024;
    const int smem_bytes = (int)sizeof(BlockSmem);

    prep_kernel<<<16, 256>>>(w3, w4, w6, c5w, f6w, rbfw);

    cudaFuncSetAttribute(lenet_kernel, cudaFuncAttributeMaxDynamicSharedMemorySize, smem_bytes);
    const int samples_per_block = WARPS_PER_BLOCK * 2;
    const int blocks = (nsamples + samples_per_block - 1) / samples_per_block;
    lenet_kernel<<<blocks, NTHREADS, smem_bytes>>>(
        x, c1w, c1b, b3, b4, b6, c5b, f6b, rbfb, out, nsamples);
}

// round 10
// speedup vs baseline: 1.3106x; 1.0236x over previous
#include <cuda_runtime.h>
#include <stdint.h>

#define WARPS_PER_BLOCK 4
#define NTHREADS (WARPS_PER_BLOCK * 32)
#define MINBLOCKS 5          // reg cap 65536/(128*5) = 102; 5 blocks/SM = 20 warps/SM
#define XST 33               // xs2 row stride in packed elements

typedef unsigned long long ull;

__device__ __forceinline__ ull pack2(float lo, float hi) {
    ull r; asm("mov.b64 %0, {%1, %2};" : "=l"(r) : "f"(lo), "f"(hi)); return r;
}
__device__ __forceinline__ void unpack2(ull v, float& lo, float& hi) {
    asm("mov.b64 {%0, %1}, %2;" : "=f"(lo), "=f"(hi) : "l"(v));
}
__device__ __forceinline__ ull fma2(ull a, ull b, ull c) {
    ull d; asm("fma.rn.f32x2 %0, %1, %2, %3;" : "=l"(d) : "l"(a), "l"(b), "l"(c)); return d;
}
__device__ __forceinline__ ull add2(ull a, ull b) {
    ull d; asm("add.rn.f32x2 %0, %1, %2;" : "=l"(d) : "l"(a), "l"(b)); return d;
}

// ---------------- precomputed tables (written by prep kernel) ----------------
__device__ uint32_t g_br_pos[60];                        // 18 (w3) + 36 (w4) + 6 (w6)
__device__ __align__(16) uint32_t g_c5_pos[120 * 16];    // transposed [o][ch]
__device__ __align__(16) float    g_f6wt[30 * 84 * 4];   // f6w tiled [j4][out][4] (coalesced)
__device__ __align__(16) float    g_rbfwt[21 * 10 * 4];  // rbfw tiled [j4][out][4]

__global__ void prep_kernel(const float* __restrict__ w3,
                            const float* __restrict__ w4,
                            const float* __restrict__ w6,
                            const float* __restrict__ c5w,
                            const float* __restrict__ f6w,
                            const float* __restrict__ rbfw) {
    const int tid = blockIdx.x * blockDim.x + threadIdx.x;
    const int stride = blockDim.x * gridDim.x;
    if (tid < 60) {
        const float* wp;
        if (tid < 18)      wp = w3 + tid * 25;
        else if (tid < 54) wp = w4 + (tid - 18) * 25;
        else               wp = w6 + (tid - 54) * 25;
        uint32_t m = 0;
        for (int i = 0; i < 25; i++) if (wp[i] > 0.0f) m |= (1u << i);
        g_br_pos[tid] = m;
    }
    for (int idx = tid; idx < 16 * 120; idx += stride) {
        int ch = idx / 120, o = idx % 120;
        const float* wp = c5w + o * 400 + ch * 25;
        uint32_t m = 0;
        for (int i = 0; i < 25; i++) if (wp[i] > 0.0f) m |= (1u << i);
        g_c5_pos[o * 16 + ch] = m;
    }
    for (int idx = tid; idx < 30 * 84 * 4; idx += stride) {
        int q = idx & 3, e = idx >> 2;
        int j4 = e / 84, i = e % 84;
        g_f6wt[idx] = f6w[i * 120 + j4 * 4 + q];
    }
    for (int idx = tid; idx < 21 * 10 * 4; idx += stride) {
        int q = idx & 3, e = idx >> 2;
        int j4 = e / 10, o = e % 10;
        g_rbfwt[idx] = rbfw[o * 84 + j4 * 4 + q];
    }
}

// ---------------- fused forward kernel: one warp = TWO samples (f32x2 packed) ------------
struct LateSmem {
    ull      sf2[120];             // c5 outputs packed as +-1.0f pairs
    ull      yv2[84];              // f6 outputs packed
    uint32_t b14[2 * 84];          // pooled 14-bit rows
    uint32_t pix[2 * 100];         // 16 branch bits per 10x10 pixel
    uint32_t cb[2 * 16];           // stage-2 pooled 25-bit words
};
struct __align__(16) WarpSmem {
    union {
        ull      xs2[32 * XST];    // packed 32x32 tile (c1 phase only), 8448B
        LateSmem L;                // post-c1 buffers
    };
    uint8_t  posm8[2 * 6 * 28 * 4];// [s][ch][row][chunk] 7-bit chunk sign masks
};
struct __align__(16) BlockSmem {
    WarpSmem w[WARPS_PER_BLOCK];
    ull      c1w2v[6][5][6];       // weights [ch][dy][k(5)+pad] for LDS.128 broadcast
    ull      c1b2[8];
    uint32_t brpos[60];
    float    brb[16];
    float    c5b[120];
};

__global__ __launch_bounds__(NTHREADS, MINBLOCKS)
void lenet_kernel(const float* __restrict__ x,
                  const float* __restrict__ c1w_g, const float* __restrict__ c1b_g,
                  const float* __restrict__ b3,   const float* __restrict__ b4,
                  const float* __restrict__ b6,   const float* __restrict__ c5b_g,
                  const float* __restrict__ f6b,
                  const float* __restrict__ rbfb,
                  float* __restrict__ out, int nsamples) {
    extern __shared__ unsigned char smem_raw[];
    BlockSmem& S = *reinterpret_cast<BlockSmem*>(smem_raw);

    const int tid = threadIdx.x;
    for (int i = tid; i < 60; i += NTHREADS)  S.brpos[i] = g_br_pos[i];
    for (int i = tid; i < 150; i += NTHREADS) {
        const int ch = i / 25, r = i % 25;
        float w = c1w_g[i];
        S.c1w2v[ch][r / 5][r % 5] = pack2(w, w);
    }
    if (tid < 30) S.c1w2v[tid / 5][tid % 5][5] = 0;
    for (int i = tid; i < 120; i += NTHREADS) S.c5b[i] = c5b_g[i];
    if (tid < 6)        { float b = c1b_g[tid]; S.c1b2[tid] = pack2(b, b); }
    if (tid < 6)        S.brb[tid] = b3[tid];
    else if (tid < 15)  S.brb[tid] = b4[tid - 6];
    else if (tid == 15) S.brb[15]  = b6[0];
    __syncthreads();

    const int warp = tid >> 5, lane = tid & 31;
    const int sA = (blockIdx.x * WARPS_PER_BLOCK + warp) * 2;
    const int sAl = min(sA, nsamples - 1);
    const int sBl = min(sA + 1, nsamples - 1);
    WarpSmem& W = S.w[warp];

    // ---- load two x tiles, interleave into packed smem ----
    {
        const float4* xgA = reinterpret_cast<const float4*>(x + (size_t)sAl * 1024);
        const float4* xgB = reinterpret_cast<const float4*>(x + (size_t)sBl * 1024);
        for (int i = lane; i < 256; i += 32) {
            float4 a = xgA[i], b = xgB[i];
            int e = i * 4;
            ull* p = W.xs2 + (e >> 5) * XST + (e & 31);
            p[0] = pack2(a.x, b.x); p[1] = pack2(a.y, b.y);
            p[2] = pack2(a.z, b.z); p[3] = pack2(a.w, b.w);
        }
    }
    __syncwarp();

    // ---- c1: packed conv; task = (3-ch group, row, 7-col chunk); 224 tasks ----
    for (int t = lane; t < 224; t += 32) {
        const int g = (t >= 112) ? 1 : 0;
        const int rc = g ? (t - 112) : t;
        const int row = rc >> 2, chunk = rc & 3;
        const int ch0 = g * 3;
        ull acc[3][7];
        #pragma unroll
        for (int c = 0; c < 3; c++) {
            const ull b2 = S.c1b2[ch0 + c];
            #pragma unroll
            for (int j = 0; j < 7; j++) acc[c][j] = b2;
        }
        const ull* xbase = W.xs2 + chunk * 7;
        #pragma unroll
        for (int dy = 0; dy < 5; dy++) {
            const ull* xr = xbase + (row + dy) * XST;
            ull xv[11];
            #pragma unroll
            for (int j = 0; j < 11; j++) xv[j] = xr[j];
            #pragma unroll
            for (int c = 0; c < 3; c++) {
                const ulonglong2* wp = reinterpret_cast<const ulonglong2*>(S.c1w2v[ch0 + c][dy]);
                const ulonglong2 w01 = wp[0], w23 = wp[1], w45 = wp[2];
                const ull wk[5] = { w01.x, w01.y, w23.x, w23.y, w45.x };
                #pragma unroll
                for (int k = 0; k < 5; k++) {
                    #pragma unroll
                    for (int col = 0; col < 7; col++)
                        acc[c][col] = fma2(xv[col + k], wk[k], acc[c][col]);
                }
            }
        }
        #pragma unroll
        for (int c = 0; c < 3; c++) {
            uint32_t mA = 0, mB = 0;
            #pragma unroll
            for (int col = 0; col < 7; col++) {
                float a, b; unpack2(acc[c][col], a, b);
                if (a > 0.0f) mA |= (1u << col);
                if (b > 0.0f) mB |= (1u << col);
            }
            const int base = (ch0 + c) * 112 + row * 4 + chunk;
            W.posm8[base]       = (uint8_t)mA;
            W.posm8[672 + base] = (uint8_t)mB;
        }
    }
    __syncwarp();   // xs2 dead from here; W.L overlays it

    // ---- stage-1 relu+avgpool+sign ----
    for (int v = lane; v < 168; v += 32) {
        const int s = (v >= 84) ? 1 : 0;
        const int u = s ? (v - 84) : v;
        const int ch = u / 14, pr = u % 14;
        const uint32_t* pm = reinterpret_cast<const uint32_t*>(W.posm8 + s * 672 + ch * 112);
        uint32_t v32 = pm[2 * pr] | pm[2 * pr + 1];
        uint32_t m = (v32 & 0x7Fu)
                   | (((v32 >> 8)  & 0x7Fu) << 7)
                   | (((v32 >> 16) & 0x7Fu) << 14)
                   | (((v32 >> 24) & 0x7Fu) << 21);
        uint32_t c = (m | (m >> 1)) & 0x55555555u;
        c = (c | (c >> 1)) & 0x33333333u;
        c = (c | (c >> 2)) & 0x0F0F0F0Fu;
        c = (c | (c >> 4)) & 0x00FF00FFu;
        c = (c | (c >> 8)) & 0x0000FFFFu;
        W.L.b14[s * 84 + u] = c;
    }
    __syncwarp();

    // ---- 16 binary branch convs: column-strip tasks, branch-outer, masks once/task ----
    // 60 tasks = 2 samples x 10 cols x 3 row-strips (rows 0-3 / 4-6 / 7-9).
    {
        const int I3[18] = {0,1,2, 1,2,3, 2,3,4, 3,4,5, 0,4,5, 0,1,5};
        const int I4[36] = {0,1,2,3, 1,2,3,4, 2,3,4,5, 0,3,4,5, 0,1,4,5,
                            0,1,2,5, 0,1,3,4, 1,2,4,5, 0,2,3,5};
        for (int t = lane; t < 60; t += 32) {
            const int s = (t >= 30) ? 1 : 0;
            const int u = s ? (t - 30) : t;
            const int col = u / 3, strip = u % 3;
            const int r0 = (strip == 0) ? 0 : (strip == 1 ? 4 : 7);
            const int nrows = (strip == 0) ? 4 : 3;
            const uint32_t* bp = W.L.b14 + s * 84;

            // packed sliding windows: rows r0..r0+6 (+row7 for 4-row strip), 5 bits each
            ull w64[6];
            #pragma unroll
            for (int ch = 0; ch < 6; ch++) {
                const uint32_t* rowp = bp + ch * 14 + r0;
                ull v = 0;
                #pragma unroll
                for (int q = 0; q < 7; q++)
                    v |= (ull)((rowp[q] >> col) & 31u) << (5 * q);
                if (nrows == 4) v |= (ull)((rowp[7] >> col) & 31u) << 35;
                w64[ch] = v;
            }
            // per-row 25-bit windows + popcounts (row 3 is junk for 3-row strips)
            uint32_t win[4][6]; int pc[4][6];
            #pragma unroll
            for (int i = 0; i < 4; i++) {
                #pragma unroll
                for (int ch = 0; ch < 6; ch++) {
                    uint32_t wv = (uint32_t)(w64[ch] >> (5 * i)) & 0x1FFFFFFu;
                    win[i][ch] = wv; pc[i][ch] = __popc(wv);
                }
            }
            uint32_t bits[4] = {0, 0, 0, 0};
            #pragma unroll
            for (int k = 0; k < 6; k++) {
                const int a = I3[3*k], b = I3[3*k+1], d = I3[3*k+2];
                const uint32_t m0 = S.brpos[3*k], m1 = S.brpos[3*k+1], m2 = S.brpos[3*k+2];
                const float bb = S.brb[k];
                #pragma unroll
                for (int i = 0; i < 4; i++) {
                    int sum = 2 * (__popc(win[i][a] & m0) + __popc(win[i][b] & m1)
                                 + __popc(win[i][d] & m2))
                              - (pc[i][a] + pc[i][b] + pc[i][d]);
                    if ((float)sum + bb > 0.0f) bits[i] |= (1u << k);
                }
            }
            #pragma unroll
            for (int k = 0; k < 9; k++) {
                const int a = I4[4*k], b = I4[4*k+1], d = I4[4*k+2], e = I4[4*k+3];
                const uint32_t m0 = S.brpos[18 + 4*k],     m1 = S.brpos[18 + 4*k + 1];
                const uint32_t m2 = S.brpos[18 + 4*k + 2], m3 = S.brpos[18 + 4*k + 3];
                const float bb = S.brb[6 + k];
                #pragma unroll
                for (int i = 0; i < 4; i++) {
                    int sum = 2 * (__popc(win[i][a] & m0) + __popc(win[i][b] & m1)
                                 + __popc(win[i][d] & m2) + __popc(win[i][e] & m3))
                              - (pc[i][a] + pc[i][b] + pc[i][d] + pc[i][e]);
                    if ((float)sum + bb > 0.0f) bits[i] |= (1u << (6 + k));
                }
            }
            {
                const float bb = S.brb[15];
                uint32_t m6[6];
                #pragma unroll
                for (int ch = 0; ch < 6; ch++) m6[ch] = S.brpos[54 + ch];
                #pragma unroll
                for (int i = 0; i < 4; i++) {
                    int sum = 0;
                    #pragma unroll
                    for (int ch = 0; ch < 6; ch++)
                        sum += 2 * __popc(win[i][ch] & m6[ch]) - pc[i][ch];
                    if ((float)sum + bb > 0.0f) bits[i] |= (1u << 15);
                }
            }
            uint32_t* pixp = W.L.pix + s * 100;
            #pragma unroll
            for (int i = 0; i < 4; i++)
                if (i < nrows) pixp[(r0 + i) * 10 + col] = bits[i];
        }
    }
    __syncwarp();

    // ---- stage-2 relu+pool+sign -> 400 bits per sample ----
    {
        const int s = lane >> 4, ch = lane & 15;
        const ull* pp2 = reinterpret_cast<const ull*>(W.L.pix + s * 100);
        uint32_t r = 0;
        #pragma unroll
        for (int u = 0; u < 25; u++) {
            const int pr = u / 5, pc2 = u % 5;
            ull pair = pp2[pr * 10 + pc2] | pp2[pr * 10 + 5 + pc2];
            uint32_t v = (uint32_t)pair | (uint32_t)(pair >> 32);
            r |= ((v >> ch) & 1u) << u;
        }
        W.L.cb[s * 16 + ch] = r;
    }
    __syncthreads();

    // ---- c5 (BLOCK-COOP): thread = output o; masks read once, reused for 4 warp-pairs ----
    if (tid < 120) {
        const int o = tid;
        uint4 p[4];
        {
            const uint4* cp = reinterpret_cast<const uint4*>(g_c5_pos + o * 16);
            #pragma unroll
            for (int q = 0; q < 4; q++) p[q] = __ldg(cp + q);
        }
        const float b = S.c5b[o];
        #pragma unroll
        for (int w4 = 0; w4 < WARPS_PER_BLOCK; w4++) {
            uint32_t cbr[32];
            const uint4* cq = reinterpret_cast<const uint4*>(S.w[w4].L.cb);
            #pragma unroll
            for (int q = 0; q < 8; q++) {
                uint4 v = cq[q];
                cbr[4*q] = v.x; cbr[4*q+1] = v.y; cbr[4*q+2] = v.z; cbr[4*q+3] = v.w;
            }
            int tpA = 0, tpB = 0;
            #pragma unroll
            for (int ch = 0; ch < 16; ch++) { tpA += __popc(cbr[ch]); tpB += __popc(cbr[16 + ch]); }
            int aA = 0, aB = 0;
            #pragma unroll
            for (int q = 0; q < 4; q++) {
                aA += __popc(cbr[4*q] & p[q].x) + __popc(cbr[4*q+1] & p[q].y)
                    + __popc(cbr[4*q+2] & p[q].z) + __popc(cbr[4*q+3] & p[q].w);
                aB += __popc(cbr[16+4*q] & p[q].x) + __popc(cbr[16+4*q+1] & p[q].y)
                    + __popc(cbr[16+4*q+2] & p[q].z) + __popc(cbr[16+4*q+3] & p[q].w);
            }
            float vA = (float)(2 * aA - tpA) + b;
            float vB = (float)(2 * aB - tpB) + b;
            S.w[w4].L.sf2[o] = pack2(vA > 0.0f ? 1.0f : -1.0f, vB > 0.0f ? 1.0f : -1.0f);
        }
    }
    __syncthreads();

    // ---- f6 (BLOCK-COOP, coalesced tiled weights): thread = output i ----
    if (tid < 84) {
        ull a0[WARPS_PER_BLOCK], a1[WARPS_PER_BLOCK];
        #pragma unroll
        for (int w4 = 0; w4 < WARPS_PER_BLOCK; w4++) { a0[w4] = 0; a1[w4] = 0; }
        const float4* wt = reinterpret_cast<const float4*>(g_f6wt) + tid;
        #pragma unroll 5
        for (int j4 = 0; j4 < 30; j4++) {
            float4 wv = __ldg(wt + j4 * 84);
            const ull wx = pack2(wv.x, wv.x), wy = pack2(wv.y, wv.y);
            const ull wz = pack2(wv.z, wv.z), ww = pack2(wv.w, wv.w);
            #pragma unroll
            for (int w4 = 0; w4 < WARPS_PER_BLOCK; w4++) {
                const ulonglong2* sp = reinterpret_cast<const ulonglong2*>(S.w[w4].L.sf2);
                ulonglong2 s01 = sp[2 * j4], s23 = sp[2 * j4 + 1];
                a0[w4] = fma2(s01.x, wx, a0[w4]);
                a1[w4] = fma2(s01.y, wy, a1[w4]);
                a0[w4] = fma2(s23.x, wz, a0[w4]);
                a1[w4] = fma2(s23.y, ww, a1[w4]);
            }
        }
        const float fb = __ldg(f6b + tid);
        #pragma unroll
        for (int w4 = 0; w4 < WARPS_PER_BLOCK; w4++) {
            float gA, gB; unpack2(add2(a0[w4], a1[w4]), gA, gB);
            S.w[w4].L.yv2[tid] = pack2(tanhf(1.7519f * (gA + fb)), tanhf(1.7519f * (gB + fb)));
        }
    }
    __syncthreads();

    // ---- rbf head (BLOCK-COOP): thread = (out o, warp-pair w4) ----
    if (tid < 10 * WARPS_PER_BLOCK) {
        const int o = tid % 10, w4 = tid / 10;
        const int s0 = (blockIdx.x * WARPS_PER_BLOCK + w4) * 2;
        const float rb = __ldg(rbfb + o);
        ull a0 = pack2(rb, rb), a1 = 0;
        const ulonglong2* yp = reinterpret_cast<const ulonglong2*>(S.w[w4].L.yv2);
        const float4* wr = reinterpret_cast<const float4*>(g_rbfwt) + o;
        #pragma unroll 7
        for (int j4 = 0; j4 < 21; j4++) {
            float4 w = __ldg(wr + j4 * 10);
            ulonglong2 y01 = yp[2 * j4];
            ulonglong2 y23 = yp[2 * j4 + 1];
            a0 = fma2(y01.x, pack2(w.x, w.x), a0);
            a1 = fma2(y01.y, pack2(w.y, w.y), a1);
            a0 = fma2(y23.x, pack2(w.z, w.z), a0);
            a1 = fma2(y23.y, pack2(w.w, w.w), a1);
        }
        float oA, oB; unpack2(add2(a0, a1), oA, oB);
        if (s0 < nsamples)     out[(size_t)s0 * 10 + o]       = fmaxf(oA, 0.0f);
        if (s0 + 1 < nsamples) out[(size_t)(s0 + 1) * 10 + o] = fmaxf(oB, 0.0f);
    }
}

extern "C" void kernel_launch(void* const* d_in, const int* in_sizes, int n_in,
                              void* d_out, int out_size) {
    const float* x    = (const float*)d_in[0];
    const float* c1w  = (const float*)d_in[1];
    const float* c1b  = (const float*)d_in[2];
    const float* w3   = (const float*)d_in[3];
    const float* b3   = (const float*)d_in[4];
    const float* w4   = (const float*)d_in[5];
    const float* b4   = (const float*)d_in[6];
    const float* w6   = (const float*)d_in[7];
    const float* b6   = (const float*)d_in[8];
    const float* c5w  = (const float*)d_in[9];
    const float* c5b  = (const float*)d_in[10];
    const float* f6w  = (const float*)d_in[11];
    const float* f6b  = (const float*)d_in[12];
    const float* rbfw = (const float*)d_in[13];
    const float* rbfb = (const float*)d_in[14];
    float* out = (float*)d_out;

    const int nsamples = in_sizes[0] / 1024;
    const int smem_bytes = (int)sizeof(BlockSmem);

    prep_kernel<<<16, 256>>>(w3, w4, w6, c5w, f6w, rbfw);

    cudaFuncSetAttribute(lenet_kernel, cudaFuncAttributeMaxDynamicSharedMemorySize, smem_bytes);
    const int samples_per_block = WARPS_PER_BLOCK * 2;
    const int blocks = (nsamples + samples_per_block - 1) / samples_per_block;
    lenet_kernel<<<blocks, NTHREADS, smem_bytes>>>(
        x, c1w, c1b, b3, b4, b6, c5b, f6b, rbfb, out, nsamples);
}